// round 14
// baseline (speedup 1.0000x reference)
#include <cuda_runtime.h>
#include <cuda_bf16.h>
#include <cstdint>

// Problem constants
#define N_SAMPLES  65536
#define START_SIZE 4096
#define N_EVENTS   32
#define STEP       (N_SAMPLES / START_SIZE)   // 16
#define ROW_F4     (N_SAMPLES / 4)            // 16384 float4 per row
#define A_THREADS  256
#define POS_F4     (START_SIZE / 4)           // 1024 float4 per event
#define A_ITERS    (POS_F4 / A_THREADS)       // 4
#define A_NWARPS   (A_THREADS / 32)           // 8

// Scratch: per-event shift in float4 units (d = idx*16 floats -> d4 = idx*4)
__device__ int g_shift4[N_EVENTS];

// Kernel A: per-event argmax over START_SIZE logits, float4-vectorized,
// single-pass (val, idx). jnp.argmax first-index tie rule.
__global__ void __launch_bounds__(A_THREADS) argmax_kernel(
    const float4* __restrict__ pos) {
    const int e   = blockIdx.x;               // 0..31
    const int tid = threadIdx.x;
    const float4* p4 = pos + (size_t)e * POS_F4;

    float    bv = __int_as_float(0xff800000); // -inf
    unsigned bi = 0u;
    #pragma unroll
    for (int kk = 0; kk < A_ITERS; kk++) {
        const int i4 = tid + kk * A_THREADS;
        const float4 v = p4[i4];
        const unsigned b = (unsigned)(i4 * 4);
        if (v.x > bv) { bv = v.x; bi = b + 0u; }
        if (v.y > bv) { bv = v.y; bi = b + 1u; }
        if (v.z > bv) { bv = v.z; bi = b + 2u; }
        if (v.w > bv) { bv = v.w; bi = b + 3u; }
    }
    #pragma unroll
    for (int off = 16; off > 0; off >>= 1) {
        const float    ov = __shfl_down_sync(0xFFFFFFFFu, bv, off);
        const unsigned oi = __shfl_down_sync(0xFFFFFFFFu, bi, off);
        if (ov > bv || (ov == bv && oi < bi)) { bv = ov; bi = oi; }
    }

    __shared__ float    s_v[A_NWARPS];
    __shared__ unsigned s_i[A_NWARPS];
    if ((tid & 31) == 0) { s_v[tid >> 5] = bv; s_i[tid >> 5] = bi; }
    __syncthreads();

    if (tid == 0) {
        float    cv = s_v[0];
        unsigned ci = s_i[0];
        #pragma unroll
        for (int w = 1; w < A_NWARPS; w++) {
            const float ov = s_v[w];
            const unsigned oi = s_i[w];
            if (ov > cv || (ov == cv && oi < ci)) { cv = ov; ci = oi; }
        }
        g_shift4[e] = (int)ci * (STEP / 4);   // shift in float4 units
    }
    // No cudaTriggerProgrammaticLaunchCompletion(): downstream
    // cudaGridDependencySynchronize() then waits for full kernel completion,
    // which guarantees g_shift4 visibility.
}

// Kernel B (PDL consumer): store-side shifted copy, float4-vectorized.
// Load is shift-independent and issued BEFORE the grid dependency sync, so
// kernel A runs entirely under our load latency.
// out[(j+d4) mod ROW_F4] = (j+d4 < ROW_F4) ? in[j] : 0
__global__ void __launch_bounds__(256) shift_copy_kernel(
    const float4* __restrict__ in, float4* __restrict__ out) {
    const int r = blockIdx.y;                  // row = b*N_EVENTS + e
    const int e = r & (N_EVENTS - 1);
    const int j = blockIdx.x * blockDim.x + threadIdx.x;   // 0..ROW_F4-1
    const size_t base = (size_t)r * ROW_F4;

    const float4 v = in[base + j];             // issued pre-sync

    cudaGridDependencySynchronize();           // wait for argmax_kernel

    const int d4 = g_shift4[e];
    const int jp = j + d4;
    if (jp < ROW_F4) {
        out[base + jp] = v;
    } else {
        out[base + jp - ROW_F4] = make_float4(0.f, 0.f, 0.f, 0.f);
    }
}

extern "C" void kernel_launch(void* const* d_in, const int* in_sizes, int n_in,
                              void* d_out, int out_size) {
    const float* events = (const float*)d_in[0];   // (B, 32, 65536) f32
    const float* pos    = (const float*)d_in[1];   // (1, 32, 4096)  f32

    const int batch = in_sizes[0] / (N_EVENTS * N_SAMPLES);   // 8
    const int rows  = batch * N_EVENTS;                       // 256

    argmax_kernel<<<N_EVENTS, A_THREADS>>>((const float4*)pos);

    // Programmatic dependent launch: B may begin while A is still running;
    // the dependency is enforced inside B by cudaGridDependencySynchronize.
    cudaLaunchConfig_t cfg = {};
    cfg.gridDim  = dim3(ROW_F4 / 256, rows, 1);
    cfg.blockDim = dim3(256, 1, 1);
    cudaLaunchAttribute attr[1];
    attr[0].id = cudaLaunchAttributeProgrammaticStreamSerialization;
    attr[0].val.programmaticStreamSerializationAllowed = 1;
    cfg.attrs    = attr;
    cfg.numAttrs = 1;
    cudaLaunchKernelEx(&cfg, shift_copy_kernel,
                       (const float4*)events, (float4*)d_out);
}

// round 16
// speedup vs baseline: 1.5529x; 1.5529x over previous
#include <cuda_runtime.h>
#include <cuda_bf16.h>
#include <cstdint>

// Problem constants
#define N_SAMPLES  65536
#define START_SIZE 4096
#define N_EVENTS   32
#define STEP       (N_SAMPLES / START_SIZE)   // 16
#define ROW_F4     (N_SAMPLES / 4)            // 16384 float4 per row
#define A_THREADS  256
#define POS_F4     (START_SIZE / 4)           // 1024 float4 per event
#define A_ITERS    (POS_F4 / A_THREADS)       // 4
#define A_NWARPS   (A_THREADS / 32)           // 8
#define B_THREADS  256
#define F4_PER_THR 2
#define BLK_F4     (B_THREADS * F4_PER_THR)   // 512 float4 per block

// Scratch: per-event shift in float4 units (d = idx*16 floats -> d4 = idx*4)
__device__ int g_shift4[N_EVENTS];

// Kernel A: per-event argmax over START_SIZE logits, float4-vectorized,
// single-pass (val, idx). jnp.argmax first-index tie rule.
__global__ void __launch_bounds__(A_THREADS) argmax_kernel(
    const float4* __restrict__ pos) {
    const int e   = blockIdx.x;               // 0..31
    const int tid = threadIdx.x;
    const float4* p4 = pos + (size_t)e * POS_F4;

    float    bv = __int_as_float(0xff800000); // -inf
    unsigned bi = 0u;
    #pragma unroll
    for (int kk = 0; kk < A_ITERS; kk++) {
        const int i4 = tid + kk * A_THREADS;
        const float4 v = p4[i4];
        const unsigned b = (unsigned)(i4 * 4);
        if (v.x > bv) { bv = v.x; bi = b + 0u; }
        if (v.y > bv) { bv = v.y; bi = b + 1u; }
        if (v.z > bv) { bv = v.z; bi = b + 2u; }
        if (v.w > bv) { bv = v.w; bi = b + 3u; }
    }
    #pragma unroll
    for (int off = 16; off > 0; off >>= 1) {
        const float    ov = __shfl_down_sync(0xFFFFFFFFu, bv, off);
        const unsigned oi = __shfl_down_sync(0xFFFFFFFFu, bi, off);
        if (ov > bv || (ov == bv && oi < bi)) { bv = ov; bi = oi; }
    }

    __shared__ float    s_v[A_NWARPS];
    __shared__ unsigned s_i[A_NWARPS];
    if ((tid & 31) == 0) { s_v[tid >> 5] = bv; s_i[tid >> 5] = bi; }
    __syncthreads();

    if (tid == 0) {
        float    cv = s_v[0];
        unsigned ci = s_i[0];
        #pragma unroll
        for (int w = 1; w < A_NWARPS; w++) {
            const float ov = s_v[w];
            const unsigned oi = s_i[w];
            if (ov > cv || (ov == cv && oi < ci)) { cv = ov; ci = oi; }
        }
        g_shift4[e] = (int)ci * (STEP / 4);   // shift in float4 units
    }
}

// Kernel B: shifted copy, 2 independent float4 per thread for MLP.
// out[r, j] = (j >= d4) ? in[r, j - d4] : 0   in float4 units.
__global__ void __launch_bounds__(B_THREADS) shift_copy_kernel(
    const float4* __restrict__ in, float4* __restrict__ out) {
    const int r  = blockIdx.y;                 // row = b*N_EVENTS + e
    const int e  = r & (N_EVENTS - 1);
    const int d4 = g_shift4[e];
    const int j0 = blockIdx.x * BLK_F4 + threadIdx.x;
    const size_t base = (size_t)r * ROW_F4;

    const int ja = j0;                         // two independent elements
    const int jb = j0 + B_THREADS;

    float4 va, vb;
    const int sa = ja - d4;
    const int sb = jb - d4;
    va = (sa >= 0) ? in[base + sa] : make_float4(0.f, 0.f, 0.f, 0.f);
    vb = (sb >= 0) ? in[base + sb] : make_float4(0.f, 0.f, 0.f, 0.f);

    out[base + ja] = va;
    out[base + jb] = vb;
}

extern "C" void kernel_launch(void* const* d_in, const int* in_sizes, int n_in,
                              void* d_out, int out_size) {
    const float* events = (const float*)d_in[0];   // (B, 32, 65536) f32
    const float* pos    = (const float*)d_in[1];   // (1, 32, 4096)  f32

    const int batch = in_sizes[0] / (N_EVENTS * N_SAMPLES);   // 8
    const int rows  = batch * N_EVENTS;                       // 256

    argmax_kernel<<<N_EVENTS, A_THREADS>>>((const float4*)pos);

    dim3 grid(ROW_F4 / BLK_F4, rows);              // 32 x 256 = 8192 blocks
    shift_copy_kernel<<<grid, B_THREADS>>>((const float4*)events,
                                           (float4*)d_out);
}